// round 6
// baseline (speedup 1.0000x reference)
#include <cuda_runtime.h>
#include <math.h>
#include <stdint.h>

#define BB 16
#define NN 1024
#define NHEADS 4
#define FIN 64
#define NHID 64
#define NCLASS 32
#define LRA 0.2f
#define FULL 0xffffffffu

// ---------------- scratch (device globals; no allocs) ----------------
__device__ __align__(16) float d_Wh1T[NHEADS*BB*NHID*NN];  // [h,b][c][j] 16.8 MB (tf32-rounded)
__device__ float d_f1[NHEADS*BB*NN];
__device__ float d_g1[NHEADS*BB*NN];
__device__ float d_is1[NHEADS*BB*NN];
__device__ __align__(16) float4 d_gv1[NHEADS*BB*NN];       // (g, e^g, e^{0.2g}, 0)
__device__ __align__(8)  float2 d_eac1[NHEADS*BB*NN];      // (e^{f-m}, e^{0.2f-m})
__device__ __align__(16) float d_hcat[BB*NN*NHEADS*NHID];  // 16.8 MB
__device__ __align__(16) float d_Wh2T[BB*NCLASS*NN];       // [b][c][j] 2 MB (tf32-rounded)
__device__ float d_f2[BB*NN];
__device__ float d_g2[BB*NN];
__device__ float d_is2[BB*NN];
__device__ __align__(16) float4 d_gv2[BB*NN];
__device__ __align__(8)  float2 d_eac2[BB*NN];
__device__ unsigned d_adjR[BB*NN*(NN/32)];   // [row][word]   2 MB
__device__ unsigned d_adjT[BB*(NN/32)*NN];   // [b][word][i]  2 MB

__device__ __forceinline__ float to_tf32(float x) {
    uint32_t r; asm("cvt.rna.tf32.f32 %0, %1;" : "=r"(r) : "f"(x));
    return __uint_as_float(r);
}
__device__ __forceinline__ uint32_t to_tf32_u(float x) {
    uint32_t r; asm("cvt.rna.tf32.f32 %0, %1;" : "=r"(r) : "f"(x));
    return r;
}
__device__ __forceinline__ void mma_tf32_16x8x8(float* d, const uint32_t* a, const uint32_t* b) {
    asm volatile(
        "mma.sync.aligned.m16n8k8.row.col.f32.tf32.tf32.f32 "
        "{%0,%1,%2,%3}, {%4,%5,%6,%7}, {%8,%9}, {%0,%1,%2,%3};"
        : "+f"(d[0]), "+f"(d[1]), "+f"(d[2]), "+f"(d[3])
        : "r"(a[0]), "r"(a[1]), "r"(a[2]), "r"(a[3]), "r"(b[0]), "r"(b[1]));
}

// ---------------- 1) pack adjacency to bitmasks (MLP=8 batches) ----------------
__global__ void pack_adj_kernel(const int* __restrict__ adj) {
    int warp = (blockIdx.x * blockDim.x + threadIdx.x) >> 5;
    int lane = threadIdx.x & 31;
    if (warp >= BB*NN) return;
    const int* row = adj + (long long)warp * NN;
    int b = warp >> 10, i = warp & 1023;
#pragma unroll
    for (int wb = 0; wb < 4; wb++) {
        int v[8];
#pragma unroll
        for (int u = 0; u < 8; u++) v[u] = row[(wb*8 + u)*32 + lane];
        unsigned m[8];
#pragma unroll
        for (int u = 0; u < 8; u++) m[u] = __ballot_sync(FULL, v[u] > 0);
        if (lane == 0) {
#pragma unroll
            for (int u = 0; u < 8; u++) {
                d_adjR[warp*32 + wb*8 + u] = m[u];
                d_adjT[(b*32 + wb*8 + u)*NN + i] = m[u];
            }
        }
    }
}

// ---------------- 2) Wh1T = (x @ W_heads[h])^T;  f,g ----------------
// grid (NN/64, BB, NHEADS), block 256
__global__ void whx1_kernel(const float* __restrict__ x,
                            const float* __restrict__ Wh,
                            const float* __restrict__ ah) {
    __shared__ __align__(16) float sW[FIN*NHID];
    __shared__ float sX[64][FIN+1];
    __shared__ float sA[2*NHID];
    int h = blockIdx.z, b = blockIdx.y, i0 = blockIdx.x*64;
    int tid = threadIdx.x;

    const float4* Wsrc = (const float4*)(Wh + (long long)h*FIN*NHID);
    float4* Wdst = (float4*)sW;
    for (int idx = tid; idx < FIN*NHID/4; idx += 256) Wdst[idx] = Wsrc[idx];
    if (tid < 2*NHID) sA[tid] = ah[h*2*NHID + tid];
    for (int idx = tid; idx < 64*FIN/4; idx += 256) {
        int r = idx >> 4, c4 = idx & 15;
        float4 v = *(const float4*)(x + (long long)(b*NN + i0 + r)*FIN + c4*4);
        sX[r][c4*4+0]=v.x; sX[r][c4*4+1]=v.y; sX[r][c4*4+2]=v.z; sX[r][c4*4+3]=v.w;
    }
    __syncthreads();

    int r = tid >> 2, ct = tid & 3, c0 = ct*16;
    float acc[16];
#pragma unroll
    for (int c = 0; c < 16; c++) acc[c] = 0.f;
#pragma unroll 4
    for (int k = 0; k < FIN; k++) {
        float xv = sX[r][k];
#pragma unroll
        for (int c4 = 0; c4 < 4; c4++) {
            float4 w = *(const float4*)(&sW[k*NHID + c0 + c4*4]);
            acc[c4*4+0] += xv*w.x; acc[c4*4+1] += xv*w.y;
            acc[c4*4+2] += xv*w.z; acc[c4*4+3] += xv*w.w;
        }
    }
    float* WT = d_Wh1T + (long long)(h*BB + b)*NHID*NN;
#pragma unroll
    for (int c = 0; c < 16; c++)
        WT[(long long)(c0 + c)*NN + i0 + r] = to_tf32(acc[c]);

    float pf = 0.f, pg = 0.f;
#pragma unroll
    for (int c = 0; c < 16; c++) { pf += acc[c]*sA[c0+c]; pg += acc[c]*sA[NHID+c0+c]; }
    pf += __shfl_xor_sync(FULL, pf, 1); pg += __shfl_xor_sync(FULL, pg, 1);
    pf += __shfl_xor_sync(FULL, pf, 2); pg += __shfl_xor_sync(FULL, pg, 2);
    if (ct == 0) {
        d_f1[(h*BB+b)*NN + i0 + r] = pf;
        d_g1[(h*BB+b)*NN + i0 + r] = pg;
    }
}

// ---------------- 3) layer-1 softmax stats (4 heads fused) ----------------
__global__ void stats1_kernel() {
    __shared__ float sG[NHEADS][NN];
    int tid = threadIdx.x;
    int warp = tid >> 5, lane = tid & 31;
    int rowg = blockIdx.x*8 + warp;
    int b = rowg >> 10, i = rowg & 1023;
    for (int idx = tid; idx < NHEADS*NN; idx += 256) {
        int hh = idx >> 10, j = idx & 1023;
        sG[hh][j] = d_g1[(hh*BB + b)*NN + j];
    }
    __syncthreads();
    unsigned word = d_adjR[rowg*32 + lane];
    float fh[NHEADS], mg[NHEADS], s[NHEADS];
#pragma unroll
    for (int hh = 0; hh < NHEADS; hh++) {
        fh[hh] = d_f1[(hh*BB+b)*NN + i]; mg[hh] = -1e30f; s[hh] = 0.f;
    }
#pragma unroll 4
    for (int w = 0; w < 32; w++) {
        unsigned ww = __shfl_sync(FULL, word, w);
        if ((ww >> lane) & 1u) {
#pragma unroll
            for (int hh = 0; hh < NHEADS; hh++)
                mg[hh] = fmaxf(mg[hh], sG[hh][w*32 + lane]);
        }
    }
#pragma unroll
    for (int off = 16; off > 0; off >>= 1)
#pragma unroll
        for (int hh = 0; hh < NHEADS; hh++)
            mg[hh] = fmaxf(mg[hh], __shfl_xor_sync(FULL, mg[hh], off));
    float m[NHEADS];
#pragma unroll
    for (int hh = 0; hh < NHEADS; hh++) {
        float xm = fh[hh] + mg[hh];
        m[hh] = xm > 0.f ? xm : LRA*xm;
    }
#pragma unroll 4
    for (int w = 0; w < 32; w++) {
        unsigned ww = __shfl_sync(FULL, word, w);
        if ((ww >> lane) & 1u) {
#pragma unroll
            for (int hh = 0; hh < NHEADS; hh++) {
                float xx = fh[hh] + sG[hh][w*32 + lane];
                float e = xx > 0.f ? xx : LRA*xx;
                s[hh] += __expf(e - m[hh]);
            }
        }
    }
#pragma unroll
    for (int off = 16; off > 0; off >>= 1)
#pragma unroll
        for (int hh = 0; hh < NHEADS; hh++)
            s[hh] += __shfl_xor_sync(FULL, s[hh], off);
    if (lane == 0) {
#pragma unroll
        for (int hh = 0; hh < NHEADS; hh++) {
            int o = (hh*BB+b)*NN + i;
            d_is1[o] = 1.0f / fmaxf(s[hh], 1e-30f);
            d_eac1[o] = make_float2(__expf(fh[hh] - m[hh]), __expf(LRA*fh[hh] - m[hh]));
            float gg = sG[hh][i];
            d_gv1[o] = make_float4(gg, __expf(gg), __expf(LRA*gg), 0.f);
        }
    }
}

// ---------------- 4) PV via mma.sync tf32 (masked softmax x Wh) ----------------
// 16 rows per warp. LAYER1: M-tile 128, 256 thr. LAYER2: M-tile 64, 128 thr.
template<int LAYER>
__global__ __launch_bounds__((LAYER == 1) ? 256 : 128)
void pv_mma_kernel(float* __restrict__ dout) {
    constexpr int F    = (LAYER == 1) ? NHID : NCLASS;
    constexpr int MT   = (LAYER == 1) ? 128 : 64;       // rows per CTA
    constexpr int NTHR = (MT/16) * 32;                  // 256 / 128
    constexpr int NT   = F / 8;                         // n-tiles of 8
    constexpr int NQ   = (32*F/4) / NTHR;               // float4 B loads per thread (=2)
    __shared__ float4 sGv[NN];                          // 16 KB (g, Eb, Ed)
    __shared__ float  sF[MT];
    __shared__ float2 sEac[MT];
    __shared__ float  sIs[MT];
    __shared__ float  sBf[2][4][NT][32][2];             // fragment-shuffled B tiles
    __shared__ unsigned sAdj[2][MT];

    const int tid = threadIdx.x, wid = tid >> 5, lane = tid & 31;
    const int g = lane >> 2, t = lane & 3;
    const int b = blockIdx.y, h = blockIdx.z, i0 = blockIdx.x * MT;
    const int hb = (LAYER == 1) ? (h*BB + b) : b;
    const float*  fA  = (LAYER == 1) ? d_f1  : d_f2;
    const float*  isA = (LAYER == 1) ? d_is1 : d_is2;
    const float2* eac = (LAYER == 1) ? d_eac1 : d_eac2;
    const float4* gvA = (LAYER == 1) ? d_gv1 : d_gv2;
    const float*  BT  = (LAYER == 1) ? (d_Wh1T + (long long)hb*F*NN)
                                     : (d_Wh2T + (long long)b*F*NN);

    for (int idx = tid; idx < NN; idx += NTHR) sGv[idx] = gvA[(long long)hb*NN + idx];
    if (tid < MT) {
        sF[tid]   = fA[(long long)hb*NN + i0 + tid];
        sEac[tid] = eac[(long long)hb*NN + i0 + tid];
        sIs[tid]  = isA[(long long)hb*NN + i0 + tid];
    }
    __syncthreads();

    // per-thread rows: wid*16 + g and wid*16 + g + 8
    float fr[2], ear[2], ecr[2];
#pragma unroll
    for (int r = 0; r < 2; r++) {
        int lr = wid*16 + g + 8*r;
        fr[r] = sF[lr]; ear[r] = sEac[lr].x; ecr[r] = sEac[lr].y;
    }

    float acc[NT][4];
#pragma unroll
    for (int nt = 0; nt < NT; nt++)
#pragma unroll
        for (int c = 0; c < 4; c++) acc[nt][c] = 0.f;

    const unsigned* adjTp = d_adjT + (long long)b*32*NN + i0 + tid;

    // prologue: prefetch chunk 0
    float4 breg[NQ];
#pragma unroll
    for (int q = 0; q < NQ; q++) {
        int idx = tid + NTHR*q; int n = idx >> 3, k4 = idx & 7;
        breg[q] = *(const float4*)(BT + (long long)n*NN + k4*4);
    }
    unsigned aw = (tid < MT) ? adjTp[0] : 0u;

#pragma unroll 1
    for (int chunk = 0; chunk < 32; chunk++) {
        const int buf = chunk & 1;
        // stage B fragments + adj words into smem
#pragma unroll
        for (int q = 0; q < NQ; q++) {
            int idx = tid + NTHR*q; int n = idx >> 3, k4 = idx & 7;
            int ks = k4 >> 1, bb = k4 & 1, nt = n >> 3, ln = (n & 7) * 4;
            sBf[buf][ks][nt][ln+0][bb] = breg[q].x;
            sBf[buf][ks][nt][ln+1][bb] = breg[q].y;
            sBf[buf][ks][nt][ln+2][bb] = breg[q].z;
            sBf[buf][ks][nt][ln+3][bb] = breg[q].w;
        }
        if (tid < MT) sAdj[buf][tid] = aw;
        __syncthreads();

        // prefetch next chunk
        if (chunk < 31) {
#pragma unroll
            for (int q = 0; q < NQ; q++) {
                int idx = tid + NTHR*q; int n = idx >> 3, k4 = idx & 7;
                breg[q] = *(const float4*)(BT + (long long)n*NN + (chunk+1)*32 + k4*4);
            }
            if (tid < MT) aw = adjTp[(long long)(chunk+1)*NN];
        }

        // my two rows' adj words (LDS broadcast within quads)
        unsigned wr[2];
        wr[0] = sAdj[buf][wid*16 + g];
        wr[1] = sAdj[buf][wid*16 + g + 8];

        // 4 k-steps of 8
#pragma unroll
        for (int s = 0; s < 4; s++) {
            const float4 gva = sGv[chunk*32 + 8*s + t];
            const float4 gvb = sGv[chunk*32 + 8*s + t + 4];
            uint32_t afr[4];
#pragma unroll
            for (int half = 0; half < 2; half++) {
                float s0 = fr[half] + gva.x;
                float p0 = (s0 > 0.f ? ear[half] : ecr[half]) * (s0 > 0.f ? gva.y : gva.z);
                p0 = ((wr[half] >> (8*s + t)) & 1u) ? p0 : 0.f;
                float s1 = fr[half] + gvb.x;
                float p1 = (s1 > 0.f ? ear[half] : ecr[half]) * (s1 > 0.f ? gvb.y : gvb.z);
                p1 = ((wr[half] >> (8*s + t + 4)) & 1u) ? p1 : 0.f;
                afr[half]     = to_tf32_u(p0);
                afr[half + 2] = to_tf32_u(p1);
            }
#pragma unroll
            for (int nt = 0; nt < NT; nt++) {
                uint32_t bf[2];
                float2 bv = *(const float2*)&sBf[buf][s][nt][lane][0];
                bf[0] = __float_as_uint(bv.x); bf[1] = __float_as_uint(bv.y);
                mma_tf32_16x8x8(acc[nt], afr, bf);
            }
        }
    }

    // epilogue: normalize (+ ELU & concat for layer 1)
#pragma unroll
    for (int half = 0; half < 2; half++) {
        int lrow = wid*16 + g + 8*half;
        int grow = i0 + lrow;
        float isv = sIs[lrow];
#pragma unroll
        for (int nt = 0; nt < NT; nt++) {
            float v0 = acc[nt][half*2+0] * isv;
            float v1 = acc[nt][half*2+1] * isv;
            if (LAYER == 1) {
                v0 = v0 > 0.f ? v0 : expm1f(v0);
                v1 = v1 > 0.f ? v1 : expm1f(v1);
                float* o = d_hcat + ((long long)(b*NN + grow))*(NHEADS*NHID) + h*NHID + nt*8 + t*2;
                *(float2*)o = make_float2(v0, v1);
            } else {
                float* o = dout + ((long long)(b*NN + grow))*NCLASS + nt*8 + t*2;
                *(float2*)o = make_float2(v0, v1);
            }
        }
    }
}

// ---------------- 5) Wh2T = (hcat @ W_out)^T;  f2,g2 ----------------
// grid BB*NN/32, block 128
__global__ void whx2_kernel(const float* __restrict__ Wo,
                            const float* __restrict__ ao) {
    __shared__ float sH[32][257];
    __shared__ float sA[2*NCLASS];
    __shared__ float sRed[32][4][2];
    int r0 = blockIdx.x * 32;
    int tid = threadIdx.x;
    int r = tid & 31, ct = tid >> 5, c0 = ct*8;
    if (tid < 2*NCLASS) sA[tid] = ao[tid];
    for (int idx = tid; idx < 32*256/4; idx += 128) {
        int rr = idx >> 6, c4 = idx & 63;
        float4 v = *(const float4*)(&d_hcat[(long long)(r0+rr)*256 + c4*4]);
        sH[rr][c4*4+0]=v.x; sH[rr][c4*4+1]=v.y; sH[rr][c4*4+2]=v.z; sH[rr][c4*4+3]=v.w;
    }
    __syncthreads();
    float acc[8];
#pragma unroll
    for (int c = 0; c < 8; c++) acc[c] = 0.f;
#pragma unroll 4
    for (int k = 0; k < 256; k++) {
        float hv = sH[r][k];
        float4 w0 = __ldg((const float4*)(Wo + k*NCLASS + c0));
        float4 w1 = __ldg((const float4*)(Wo + k*NCLASS + c0 + 4));
        acc[0]+=hv*w0.x; acc[1]+=hv*w0.y; acc[2]+=hv*w0.z; acc[3]+=hv*w0.w;
        acc[4]+=hv*w1.x; acc[5]+=hv*w1.y; acc[6]+=hv*w1.z; acc[7]+=hv*w1.w;
    }
    int b = r0 >> 10;
    int j = (r0 & 1023) + r;
#pragma unroll
    for (int c = 0; c < 8; c++)
        d_Wh2T[((long long)b*NCLASS + c0 + c)*NN + j] = to_tf32(acc[c]);
    float pf = 0.f, pg = 0.f;
#pragma unroll
    for (int c = 0; c < 8; c++) { pf += acc[c]*sA[c0+c]; pg += acc[c]*sA[NCLASS+c0+c]; }
    sRed[r][ct][0] = pf; sRed[r][ct][1] = pg;
    __syncthreads();
    if (tid < 32) {
        float f = sRed[tid][0][0]+sRed[tid][1][0]+sRed[tid][2][0]+sRed[tid][3][0];
        float g = sRed[tid][0][1]+sRed[tid][1][1]+sRed[tid][2][1]+sRed[tid][3][1];
        d_f2[r0+tid] = f; d_g2[r0+tid] = g;
    }
}

// ---------------- 6) layer-2 softmax stats ----------------
__global__ void stats2_kernel() {
    __shared__ float sG[NN];
    int tid = threadIdx.x;
    int warp = tid >> 5, lane = tid & 31;
    int rowg = blockIdx.x*8 + warp;
    int b = rowg >> 10;
    for (int idx = tid; idx < NN; idx += 256) sG[idx] = d_g2[b*NN + idx];
    __syncthreads();
    unsigned word = d_adjR[rowg*32 + lane];
    float fv = d_f2[rowg];
    float mg = -1e30f;
#pragma unroll 4
    for (int w = 0; w < 32; w++) {
        unsigned ww = __shfl_sync(FULL, word, w);
        if ((ww >> lane) & 1u) mg = fmaxf(mg, sG[w*32 + lane]);
    }
#pragma unroll
    for (int off = 16; off > 0; off >>= 1)
        mg = fmaxf(mg, __shfl_xor_sync(FULL, mg, off));
    float xm = fv + mg;
    float m = xm > 0.f ? xm : LRA*xm;
    float s = 0.f;
#pragma unroll 4
    for (int w = 0; w < 32; w++) {
        unsigned ww = __shfl_sync(FULL, word, w);
        if ((ww >> lane) & 1u) {
            float xx = fv + sG[w*32 + lane];
            float e = xx > 0.f ? xx : LRA*xx;
            s += __expf(e - m);
        }
    }
#pragma unroll
    for (int off = 16; off > 0; off >>= 1)
        s += __shfl_xor_sync(FULL, s, off);
    if (lane == 0) {
        int i = rowg & 1023;
        d_is2[rowg] = 1.0f/fmaxf(s, 1e-30f);
        d_eac2[rowg] = make_float2(__expf(fv - m), __expf(LRA*fv - m));
        float gg = sG[i];
        d_gv2[rowg] = make_float4(gg, __expf(gg), __expf(LRA*gg), 0.f);
    }
}

// ---------------- launch ----------------
extern "C" void kernel_launch(void* const* d_in, const int* in_sizes, int n_in,
                              void* d_out, int out_size) {
    (void)in_sizes; (void)n_in; (void)out_size;
    const float* x       = (const float*)d_in[0];
    const int*   adj     = (const int*)  d_in[1];
    const float* W_heads = (const float*)d_in[2];
    const float* a_heads = (const float*)d_in[3];
    const float* W_out   = (const float*)d_in[4];
    const float* a_out   = (const float*)d_in[5];
    float* out = (float*)d_out;

    pack_adj_kernel<<<BB*NN/8, 256>>>(adj);
    whx1_kernel<<<dim3(NN/64, BB, NHEADS), 256>>>(x, W_heads, a_heads);
    stats1_kernel<<<BB*NN/8, 256>>>();
    pv_mma_kernel<1><<<dim3(NN/128, BB, NHEADS), 256>>>(nullptr);
    whx2_kernel<<<BB*NN/32, 128>>>(W_out, a_out);
    stats2_kernel<<<BB*NN/8, 256>>>();
    pv_mma_kernel<2><<<dim3(NN/64, BB, 1), 128>>>(out);
}

// round 8
// speedup vs baseline: 1.2359x; 1.2359x over previous
#include <cuda_runtime.h>
#include <math.h>
#include <stdint.h>

#define BB 16
#define NN 1024
#define NHEADS 4
#define FIN 64
#define NHID 64
#define NCLASS 32
#define LRA 0.2f
#define FULL 0xffffffffu

// ---------------- scratch (device globals; no allocs) ----------------
__device__ __align__(16) float d_Wh1T[NHEADS*BB*NHID*NN];  // [h,b][c][j] 16.8 MB (tf32)
__device__ float d_f1[NHEADS*BB*NN];
__device__ __align__(8)  float2 d_eac1[NHEADS*BB*NN];      // (e^f, e^{0.2f})
__device__ __align__(16) float4 d_gv1[NHEADS*BB*NN];       // (g, e^g, e^{0.2g}, 0)
__device__ __align__(16) float d_hcat[BB*NN*NHEADS*NHID];  // 16.8 MB
__device__ __align__(16) float d_Wh2T[BB*NCLASS*NN];       // [b][c][j] 2 MB (tf32)
__device__ float d_f2[BB*NN];
__device__ __align__(8)  float2 d_eac2[BB*NN];
__device__ __align__(16) float4 d_gv2[BB*NN];
__device__ unsigned d_adjT[BB*(NN/32)*NN];   // [b][word][i]  2 MB

__device__ __forceinline__ float to_tf32(float x) {
    uint32_t r; asm("cvt.rna.tf32.f32 %0, %1;" : "=r"(r) : "f"(x));
    return __uint_as_float(r);
}
__device__ __forceinline__ uint32_t to_tf32_u(float x) {
    uint32_t r; asm("cvt.rna.tf32.f32 %0, %1;" : "=r"(r) : "f"(x));
    return r;
}
__device__ __forceinline__ void mma_tf32_16x8x8(float* d, const uint32_t* a, const uint32_t* b) {
    asm volatile(
        "mma.sync.aligned.m16n8k8.row.col.f32.tf32.tf32.f32 "
        "{%0,%1,%2,%3}, {%4,%5,%6,%7}, {%8,%9}, {%0,%1,%2,%3};"
        : "+f"(d[0]), "+f"(d[1]), "+f"(d[2]), "+f"(d[3])
        : "r"(a[0]), "r"(a[1]), "r"(a[2]), "r"(a[3]), "r"(b[0]), "r"(b[1]));
}

// ---------------- 1) pack adjacency to transposed bitmask ----------------
__global__ void pack_adj_kernel(const int* __restrict__ adj) {
    int warp = (blockIdx.x * blockDim.x + threadIdx.x) >> 5;
    int lane = threadIdx.x & 31;
    if (warp >= BB*NN) return;
    const int* row = adj + (long long)warp * NN;
    int b = warp >> 10, i = warp & 1023;
    unsigned mym = 0;
#pragma unroll
    for (int wb = 0; wb < 4; wb++) {
        int v[8];
#pragma unroll
        for (int u = 0; u < 8; u++) v[u] = row[(wb*8 + u)*32 + lane];
#pragma unroll
        for (int u = 0; u < 8; u++) {
            unsigned m = __ballot_sync(FULL, v[u] > 0);
            if (lane == wb*8 + u) mym = m;
        }
    }
    // ballot result is warp-uniform; lane w owns word w -> one parallel store
    d_adjT[(b*32 + lane)*NN + i] = mym;
}

// ---------------- 2) Wh1T = (x @ W_heads[h])^T;  f,g + exps ----------------
// grid (NN/64, BB, NHEADS), block 256
__global__ void whx1_kernel(const float* __restrict__ x,
                            const float* __restrict__ Wh,
                            const float* __restrict__ ah) {
    __shared__ __align__(16) float sW[FIN*NHID];   // 16 KB
    __shared__ float sX[64][FIN+1];                // 16.6 KB; reused as transpose buffer
    __shared__ float sA[2*NHID];
    int h = blockIdx.z, b = blockIdx.y, i0 = blockIdx.x*64;
    int tid = threadIdx.x;

    const float4* Wsrc = (const float4*)(Wh + (long long)h*FIN*NHID);
    float4* Wdst = (float4*)sW;
    for (int idx = tid; idx < FIN*NHID/4; idx += 256) Wdst[idx] = Wsrc[idx];
    if (tid < 2*NHID) sA[tid] = ah[h*2*NHID + tid];
    for (int idx = tid; idx < 64*FIN/4; idx += 256) {
        int r = idx >> 4, c4 = idx & 15;
        float4 v = *(const float4*)(x + (long long)(b*NN + i0 + r)*FIN + c4*4);
        sX[r][c4*4+0]=v.x; sX[r][c4*4+1]=v.y; sX[r][c4*4+2]=v.z; sX[r][c4*4+3]=v.w;
    }
    __syncthreads();

    int r = tid >> 2, ct = tid & 3, c0 = ct*16;
    float acc[16];
#pragma unroll
    for (int c = 0; c < 16; c++) acc[c] = 0.f;
#pragma unroll 4
    for (int k = 0; k < FIN; k++) {
        float xv = sX[r][k];
#pragma unroll
        for (int c4 = 0; c4 < 4; c4++) {
            float4 w = *(const float4*)(&sW[k*NHID + c0 + c4*4]);
            acc[c4*4+0] += xv*w.x; acc[c4*4+1] += xv*w.y;
            acc[c4*4+2] += xv*w.z; acc[c4*4+3] += xv*w.w;
        }
    }

    // f,g reduction (registers only)
    float pf = 0.f, pg = 0.f;
#pragma unroll
    for (int c = 0; c < 16; c++) { pf += acc[c]*sA[c0+c]; pg += acc[c]*sA[NHID+c0+c]; }
    pf += __shfl_xor_sync(FULL, pf, 1); pg += __shfl_xor_sync(FULL, pg, 1);
    pf += __shfl_xor_sync(FULL, pf, 2); pg += __shfl_xor_sync(FULL, pg, 2);
    if (ct == 0) {
        int o = (h*BB+b)*NN + i0 + r;
        d_f1[o] = pf;
        d_eac1[o] = make_float2(__expf(pf), __expf(LRA*pf));
        d_gv1[o] = make_float4(pg, __expf(pg), __expf(LRA*pg), 0.f);
    }

    // transpose through smem (reuse sX), then coalesced float4 stores
    __syncthreads();
#pragma unroll
    for (int c = 0; c < 16; c++) sX[c0 + c][r] = to_tf32(acc[c]);
    __syncthreads();
    float* WT = d_Wh1T + (long long)(h*BB + b)*NHID*NN;
    for (int idx = tid; idx < 64*16; idx += 256) {
        int c = idx >> 4, j4 = idx & 15;
        float4 v = make_float4(sX[c][j4*4], sX[c][j4*4+1], sX[c][j4*4+2], sX[c][j4*4+3]);
        *(float4*)(WT + (long long)c*NN + i0 + j4*4) = v;
    }
}

// ---------------- 3) PV via mma.sync tf32 + ones-column row sums ----------------
// 16 rows/warp. LAYER1: M-tile 128, 256 thr. LAYER2: M-tile 64, 128 thr.
template<int LAYER>
__global__ __launch_bounds__((LAYER == 1) ? 256 : 128)
void pv_mma_kernel(float* __restrict__ dout) {
    constexpr int F    = (LAYER == 1) ? NHID : NCLASS;
    constexpr int MT   = (LAYER == 1) ? 128 : 64;
    constexpr int NTHR = (MT/16) * 32;
    constexpr int NT   = F / 8;
    constexpr int NQ   = (32*F/4) / NTHR;               // = 2
    __shared__ float4 sGv[NN];                          // 16 KB
    __shared__ float  sF[MT];
    __shared__ float2 sEac[MT];
    __shared__ float  sBf[2][4][NT][32][2];
    __shared__ unsigned sAdj[2][MT];
    __shared__ float  sS[MT];

    const int tid = threadIdx.x, wid = tid >> 5, lane = tid & 31;
    const int g = lane >> 2, t = lane & 3;
    const int b = blockIdx.y, h = blockIdx.z, i0 = blockIdx.x * MT;
    const int hb = (LAYER == 1) ? (h*BB + b) : b;
    const float*  fA  = (LAYER == 1) ? d_f1  : d_f2;
    const float2* eac = (LAYER == 1) ? d_eac1 : d_eac2;
    const float4* gvA = (LAYER == 1) ? d_gv1 : d_gv2;
    const float*  BT  = (LAYER == 1) ? (d_Wh1T + (long long)hb*F*NN)
                                     : (d_Wh2T + (long long)b*F*NN);

    for (int idx = tid; idx < NN; idx += NTHR) sGv[idx] = gvA[(long long)hb*NN + idx];
    if (tid < MT) {
        sF[tid]   = fA[(long long)hb*NN + i0 + tid];
        sEac[tid] = eac[(long long)hb*NN + i0 + tid];
    }
    __syncthreads();

    float fr[2], ear[2], ecr[2];
#pragma unroll
    for (int r = 0; r < 2; r++) {
        int lr = wid*16 + g + 8*r;
        fr[r] = sF[lr]; ear[r] = sEac[lr].x; ecr[r] = sEac[lr].y;
    }

    float acc[NT][4], accS[4];
#pragma unroll
    for (int nt = 0; nt < NT; nt++)
#pragma unroll
        for (int c = 0; c < 4; c++) acc[nt][c] = 0.f;
#pragma unroll
    for (int c = 0; c < 4; c++) accS[c] = 0.f;
    // ones-column B fragment (col 0 of the extra n-tile = 1)
    uint32_t bone[2];
    bone[0] = bone[1] = (lane < 4) ? 0x3f800000u : 0u;

    const unsigned* adjTp = d_adjT + (long long)b*32*NN + i0 + tid;

    float4 breg[NQ];
#pragma unroll
    for (int q = 0; q < NQ; q++) {
        int idx = tid + NTHR*q; int n = idx >> 3, k4 = idx & 7;
        breg[q] = *(const float4*)(BT + (long long)n*NN + k4*4);
    }
    unsigned aw = (tid < MT) ? adjTp[0] : 0u;

#pragma unroll 1
    for (int chunk = 0; chunk < 32; chunk++) {
        const int buf = chunk & 1;
#pragma unroll
        for (int q = 0; q < NQ; q++) {
            int idx = tid + NTHR*q; int n = idx >> 3, k4 = idx & 7;
            int ks = k4 >> 1, bb = k4 & 1, nt = n >> 3, ln = (n & 7) * 4;
            sBf[buf][ks][nt][ln+0][bb] = breg[q].x;
            sBf[buf][ks][nt][ln+1][bb] = breg[q].y;
            sBf[buf][ks][nt][ln+2][bb] = breg[q].z;
            sBf[buf][ks][nt][ln+3][bb] = breg[q].w;
        }
        if (tid < MT) sAdj[buf][tid] = aw;
        __syncthreads();

        if (chunk < 31) {
#pragma unroll
            for (int q = 0; q < NQ; q++) {
                int idx = tid + NTHR*q; int n = idx >> 3, k4 = idx & 7;
                breg[q] = *(const float4*)(BT + (long long)n*NN + (chunk+1)*32 + k4*4);
            }
            if (tid < MT) aw = adjTp[(long long)(chunk+1)*NN];
        }

        unsigned wr[2];
        wr[0] = sAdj[buf][wid*16 + g];
        wr[1] = sAdj[buf][wid*16 + g + 8];

#pragma unroll
        for (int s = 0; s < 4; s++) {
            const float4 gva = sGv[chunk*32 + 8*s + t];
            const float4 gvb = sGv[chunk*32 + 8*s + t + 4];
            uint32_t afr[4];
#pragma unroll
            for (int half = 0; half < 2; half++) {
                float s0 = fr[half] + gva.x;
                float p0 = (s0 > 0.f ? ear[half] : ecr[half]) * (s0 > 0.f ? gva.y : gva.z);
                p0 = ((wr[half] >> (8*s + t)) & 1u) ? p0 : 0.f;
                float s1 = fr[half] + gvb.x;
                float p1 = (s1 > 0.f ? ear[half] : ecr[half]) * (s1 > 0.f ? gvb.y : gvb.z);
                p1 = ((wr[half] >> (8*s + t + 4)) & 1u) ? p1 : 0.f;
                afr[half]     = to_tf32_u(p0);
                afr[half + 2] = to_tf32_u(p1);
            }
#pragma unroll
            for (int nt = 0; nt < NT; nt++) {
                uint32_t bf[2];
                float2 bv = *(const float2*)&sBf[buf][s][nt][lane][0];
                bf[0] = __float_as_uint(bv.x); bf[1] = __float_as_uint(bv.y);
                mma_tf32_16x8x8(acc[nt], afr, bf);
            }
            mma_tf32_16x8x8(accS, afr, bone);   // row sums
        }
    }

    // share row sums (col 0 lives in t==0 threads)
    if (t == 0) {
        sS[wid*16 + g]     = accS[0];
        sS[wid*16 + g + 8] = accS[2];
    }
    __syncthreads();

    // epilogue: normalize (+ ELU & concat for layer 1)
#pragma unroll
    for (int half = 0; half < 2; half++) {
        int lrow = wid*16 + g + 8*half;
        int grow = i0 + lrow;
        float isv = 1.0f / fmaxf(sS[lrow], 1e-30f);
#pragma unroll
        for (int nt = 0; nt < NT; nt++) {
            float v0 = acc[nt][half*2+0] * isv;
            float v1 = acc[nt][half*2+1] * isv;
            if (LAYER == 1) {
                v0 = v0 > 0.f ? v0 : expm1f(v0);
                v1 = v1 > 0.f ? v1 : expm1f(v1);
                float* o = d_hcat + ((long long)(b*NN + grow))*(NHEADS*NHID) + h*NHID + nt*8 + t*2;
                *(float2*)o = make_float2(v0, v1);
            } else {
                float* o = dout + ((long long)(b*NN + grow))*NCLASS + nt*8 + t*2;
                *(float2*)o = make_float2(v0, v1);
            }
        }
    }
}

// ---------------- 4) Wh2T = (hcat @ W_out)^T;  f2,g2 + exps ----------------
// grid BB*NN/32, block 128
__global__ void whx2_kernel(const float* __restrict__ Wo,
                            const float* __restrict__ ao) {
    __shared__ float sH[32][257];      // 33 KB
    __shared__ float sT[32][33];       // 4.2 KB transpose staging
    __shared__ float sA[2*NCLASS];
    __shared__ float sRed[32][4][2];
    int r0 = blockIdx.x * 32;
    int tid = threadIdx.x;
    int r = tid & 31, ct = tid >> 5, c0 = ct*8;
    if (tid < 2*NCLASS) sA[tid] = ao[tid];
    for (int idx = tid; idx < 32*256/4; idx += 128) {
        int rr = idx >> 6, c4 = idx & 63;
        float4 v = *(const float4*)(&d_hcat[(long long)(r0+rr)*256 + c4*4]);
        sH[rr][c4*4+0]=v.x; sH[rr][c4*4+1]=v.y; sH[rr][c4*4+2]=v.z; sH[rr][c4*4+3]=v.w;
    }
    __syncthreads();
    float acc[8];
#pragma unroll
    for (int c = 0; c < 8; c++) acc[c] = 0.f;
#pragma unroll 4
    for (int k = 0; k < 256; k++) {
        float hv = sH[r][k];
        float4 w0 = __ldg((const float4*)(Wo + k*NCLASS + c0));
        float4 w1 = __ldg((const float4*)(Wo + k*NCLASS + c0 + 4));
        acc[0]+=hv*w0.x; acc[1]+=hv*w0.y; acc[2]+=hv*w0.z; acc[3]+=hv*w0.w;
        acc[4]+=hv*w1.x; acc[5]+=hv*w1.y; acc[6]+=hv*w1.z; acc[7]+=hv*w1.w;
    }
    int b = r0 >> 10;
    int j0 = r0 & 1023;

    // transpose staging + coalesced stores
#pragma unroll
    for (int c = 0; c < 8; c++) sT[c0 + c][r] = to_tf32(acc[c]);

    float pf = 0.f, pg = 0.f;
#pragma unroll
    for (int c = 0; c < 8; c++) { pf += acc[c]*sA[c0+c]; pg += acc[c]*sA[NCLASS+c0+c]; }
    sRed[r][ct][0] = pf; sRed[r][ct][1] = pg;
    __syncthreads();

    // 32 cols x 8 float4-groups = 256 stores; strided over 128 threads (BUGFIX)
    for (int idx = tid; idx < 32*8; idx += 128) {
        int c = idx >> 3, j4 = idx & 7;
        float4 v = make_float4(sT[c][j4*4], sT[c][j4*4+1], sT[c][j4*4+2], sT[c][j4*4+3]);
        *(float4*)(d_Wh2T + ((long long)b*NCLASS + c)*NN + j0 + j4*4) = v;
    }
    if (tid < 32) {
        float f = sRed[tid][0][0]+sRed[tid][1][0]+sRed[tid][2][0]+sRed[tid][3][0];
        float g = sRed[tid][0][1]+sRed[tid][1][1]+sRed[tid][2][1]+sRed[tid][3][1];
        int o = r0 + tid;
        d_f2[o] = f;
        d_eac2[o] = make_float2(__expf(f), __expf(LRA*f));
        d_gv2[o] = make_float4(g, __expf(g), __expf(LRA*g), 0.f);
    }
}

// ---------------- launch ----------------
extern "C" void kernel_launch(void* const* d_in, const int* in_sizes, int n_in,
                              void* d_out, int out_size) {
    (void)in_sizes; (void)n_in; (void)out_size;
    const float* x       = (const float*)d_in[0];
    const int*   adj     = (const int*)  d_in[1];
    const float* W_heads = (const float*)d_in[2];
    const float* a_heads = (const float*)d_in[3];
    const float* W_out   = (const float*)d_in[4];
    const float* a_out   = (const float*)d_in[5];
    float* out = (float*)d_out;

    pack_adj_kernel<<<BB*NN/8, 256>>>(adj);
    whx1_kernel<<<dim3(NN/64, BB, NHEADS), 256>>>(x, W_heads, a_heads);
    pv_mma_kernel<1><<<dim3(NN/128, BB, NHEADS), 256>>>(nullptr);
    whx2_kernel<<<BB*NN/32, 128>>>(W_out, a_out);
    pv_mma_kernel<2><<<dim3(NN/64, BB, 1), 128>>>(out);
}

// round 9
// speedup vs baseline: 1.3496x; 1.0920x over previous
#include <cuda_runtime.h>
#include <math.h>
#include <stdint.h>

#define BB 16
#define NN 1024
#define NHEADS 4
#define FIN 64
#define NHID 64
#define NCLASS 32
#define LRA 0.2f
#define FULL 0xffffffffu

// ---------------- scratch (device globals; no allocs) ----------------
__device__ __align__(16) float d_Wh1T[NHEADS*BB*NHID*NN];  // [h,b][c][j] 16.8 MB (tf32)
__device__ float d_f1[NHEADS*BB*NN];
__device__ __align__(8)  float2 d_eac1[NHEADS*BB*NN];      // (e^f, e^{0.2f})
__device__ __align__(16) float4 d_gv1[NHEADS*BB*NN];       // (g, e^g, e^{0.2g}, 0)
__device__ __align__(16) float d_hcat[BB*NN*NHEADS*NHID];  // 16.8 MB
__device__ __align__(16) float d_Wh2T[BB*NCLASS*NN];       // [b][c][j] 2 MB (tf32)
__device__ float d_f2[BB*NN];
__device__ __align__(8)  float2 d_eac2[BB*NN];
__device__ __align__(16) float4 d_gv2[BB*NN];
__device__ unsigned d_adjT[BB*(NN/32)*NN];   // [b][word][i]  2 MB

__device__ __forceinline__ float to_tf32(float x) {
    uint32_t r; asm("cvt.rna.tf32.f32 %0, %1;" : "=r"(r) : "f"(x));
    return __uint_as_float(r);
}
__device__ __forceinline__ uint32_t to_tf32_u(float x) {
    uint32_t r; asm("cvt.rna.tf32.f32 %0, %1;" : "=r"(r) : "f"(x));
    return r;
}
__device__ __forceinline__ void mma_tf32_16x8x8(float* d, const uint32_t* a, const uint32_t* b) {
    asm volatile(
        "mma.sync.aligned.m16n8k8.row.col.f32.tf32.tf32.f32 "
        "{%0,%1,%2,%3}, {%4,%5,%6,%7}, {%8,%9}, {%0,%1,%2,%3};"
        : "+f"(d[0]), "+f"(d[1]), "+f"(d[2]), "+f"(d[3])
        : "r"(a[0]), "r"(a[1]), "r"(a[2]), "r"(a[3]), "r"(b[0]), "r"(b[1]));
}

// ---------------- 1) pack adjacency to transposed bitmask ----------------
__global__ void pack_adj_kernel(const int* __restrict__ adj) {
    int warp = (blockIdx.x * blockDim.x + threadIdx.x) >> 5;
    int lane = threadIdx.x & 31;
    if (warp >= BB*NN) return;
    const int* row = adj + (long long)warp * NN;
    int b = warp >> 10, i = warp & 1023;
    unsigned mym = 0;
#pragma unroll
    for (int wb = 0; wb < 4; wb++) {
        int v[8];
#pragma unroll
        for (int u = 0; u < 8; u++) v[u] = row[(wb*8 + u)*32 + lane];
#pragma unroll
        for (int u = 0; u < 8; u++) {
            unsigned m = __ballot_sync(FULL, v[u] > 0);
            if (lane == wb*8 + u) mym = m;
        }
    }
    d_adjT[(b*32 + lane)*NN + i] = mym;
}

// ---------------- 2) Wh1T = (x @ W_heads[h])^T;  f,g + exps ----------------
// grid (NN/64, BB, NHEADS), block 256
__global__ void whx1_kernel(const float* __restrict__ x,
                            const float* __restrict__ Wh,
                            const float* __restrict__ ah) {
    __shared__ __align__(16) float sW[FIN*NHID];   // 16 KB
    __shared__ float sX[64][FIN+1];                // 16.6 KB; reused as transpose buffer
    __shared__ float sA[2*NHID];
    int h = blockIdx.z, b = blockIdx.y, i0 = blockIdx.x*64;
    int tid = threadIdx.x;

    const float4* Wsrc = (const float4*)(Wh + (long long)h*FIN*NHID);
    float4* Wdst = (float4*)sW;
    for (int idx = tid; idx < FIN*NHID/4; idx += 256) Wdst[idx] = Wsrc[idx];
    if (tid < 2*NHID) sA[tid] = ah[h*2*NHID + tid];
    for (int idx = tid; idx < 64*FIN/4; idx += 256) {
        int r = idx >> 4, c4 = idx & 15;
        float4 v = *(const float4*)(x + (long long)(b*NN + i0 + r)*FIN + c4*4);
        sX[r][c4*4+0]=v.x; sX[r][c4*4+1]=v.y; sX[r][c4*4+2]=v.z; sX[r][c4*4+3]=v.w;
    }
    __syncthreads();

    int r = tid >> 2, ct = tid & 3, c0 = ct*16;
    float acc[16];
#pragma unroll
    for (int c = 0; c < 16; c++) acc[c] = 0.f;
#pragma unroll 4
    for (int k = 0; k < FIN; k++) {
        float xv = sX[r][k];
#pragma unroll
        for (int c4 = 0; c4 < 4; c4++) {
            float4 w = *(const float4*)(&sW[k*NHID + c0 + c4*4]);
            acc[c4*4+0] += xv*w.x; acc[c4*4+1] += xv*w.y;
            acc[c4*4+2] += xv*w.z; acc[c4*4+3] += xv*w.w;
        }
    }

    float pf = 0.f, pg = 0.f;
#pragma unroll
    for (int c = 0; c < 16; c++) { pf += acc[c]*sA[c0+c]; pg += acc[c]*sA[NHID+c0+c]; }
    pf += __shfl_xor_sync(FULL, pf, 1); pg += __shfl_xor_sync(FULL, pg, 1);
    pf += __shfl_xor_sync(FULL, pf, 2); pg += __shfl_xor_sync(FULL, pg, 2);
    if (ct == 0) {
        int o = (h*BB+b)*NN + i0 + r;
        d_f1[o] = pf;
        d_eac1[o] = make_float2(__expf(pf), __expf(LRA*pf));
        d_gv1[o] = make_float4(pg, __expf(pg), __expf(LRA*pg), 0.f);
    }

    __syncthreads();
#pragma unroll
    for (int c = 0; c < 16; c++) sX[c0 + c][r] = to_tf32(acc[c]);
    __syncthreads();
    float* WT = d_Wh1T + (long long)(h*BB + b)*NHID*NN;
    for (int idx = tid; idx < 64*16; idx += 256) {
        int c = idx >> 4, j4 = idx & 15;
        float4 v = make_float4(sX[c][j4*4], sX[c][j4*4+1], sX[c][j4*4+2], sX[c][j4*4+3]);
        *(float4*)(WT + (long long)c*NN + i0 + j4*4) = v;
    }
}

// ---------------- 3) PV via mma.sync tf32 + ones-column row sums ----------------
template<int LAYER>
__global__ __launch_bounds__((LAYER == 1) ? 256 : 128)
void pv_mma_kernel(float* __restrict__ dout) {
    constexpr int F    = (LAYER == 1) ? NHID : NCLASS;
    constexpr int MT   = (LAYER == 1) ? 128 : 64;
    constexpr int NTHR = (MT/16) * 32;
    constexpr int NT   = F / 8;
    constexpr int NQ   = (32*F/4) / NTHR;               // = 2
    __shared__ float4 sGv[NN];
    __shared__ float  sF[MT];
    __shared__ float2 sEac[MT];
    __shared__ float  sBf[2][4][NT][32][2];
    __shared__ unsigned sAdj[2][MT];
    __shared__ float  sS[MT];

    const int tid = threadIdx.x, wid = tid >> 5, lane = tid & 31;
    const int g = lane >> 2, t = lane & 3;
    const int b = blockIdx.y, h = blockIdx.z, i0 = blockIdx.x * MT;
    const int hb = (LAYER == 1) ? (h*BB + b) : b;
    const float*  fA  = (LAYER == 1) ? d_f1  : d_f2;
    const float2* eac = (LAYER == 1) ? d_eac1 : d_eac2;
    const float4* gvA = (LAYER == 1) ? d_gv1 : d_gv2;
    const float*  BT  = (LAYER == 1) ? (d_Wh1T + (long long)hb*F*NN)
                                     : (d_Wh2T + (long long)b*F*NN);

    for (int idx = tid; idx < NN; idx += NTHR) sGv[idx] = gvA[(long long)hb*NN + idx];
    if (tid < MT) {
        sF[tid]   = fA[(long long)hb*NN + i0 + tid];
        sEac[tid] = eac[(long long)hb*NN + i0 + tid];
    }
    __syncthreads();

    float fr[2], ear[2], ecr[2];
#pragma unroll
    for (int r = 0; r < 2; r++) {
        int lr = wid*16 + g + 8*r;
        fr[r] = sF[lr]; ear[r] = sEac[lr].x; ecr[r] = sEac[lr].y;
    }

    float acc[NT][4], accS[4];
#pragma unroll
    for (int nt = 0; nt < NT; nt++)
#pragma unroll
        for (int c = 0; c < 4; c++) acc[nt][c] = 0.f;
#pragma unroll
    for (int c = 0; c < 4; c++) accS[c] = 0.f;
    uint32_t bone[2];
    bone[0] = bone[1] = (lane < 4) ? 0x3f800000u : 0u;

    const unsigned* adjTp = d_adjT + (long long)b*32*NN + i0 + tid;

    float4 breg[NQ];
#pragma unroll
    for (int q = 0; q < NQ; q++) {
        int idx = tid + NTHR*q; int n = idx >> 3, k4 = idx & 7;
        breg[q] = *(const float4*)(BT + (long long)n*NN + k4*4);
    }
    unsigned aw = (tid < MT) ? adjTp[0] : 0u;

#pragma unroll 1
    for (int chunk = 0; chunk < 32; chunk++) {
        const int buf = chunk & 1;
#pragma unroll
        for (int q = 0; q < NQ; q++) {
            int idx = tid + NTHR*q; int n = idx >> 3, k4 = idx & 7;
            int ks = k4 >> 1, bb = k4 & 1, nt = n >> 3, ln = (n & 7) * 4;
            sBf[buf][ks][nt][ln+0][bb] = breg[q].x;
            sBf[buf][ks][nt][ln+1][bb] = breg[q].y;
            sBf[buf][ks][nt][ln+2][bb] = breg[q].z;
            sBf[buf][ks][nt][ln+3][bb] = breg[q].w;
        }
        if (tid < MT) sAdj[buf][tid] = aw;
        __syncthreads();

        if (chunk < 31) {
#pragma unroll
            for (int q = 0; q < NQ; q++) {
                int idx = tid + NTHR*q; int n = idx >> 3, k4 = idx & 7;
                breg[q] = *(const float4*)(BT + (long long)n*NN + (chunk+1)*32 + k4*4);
            }
            if (tid < MT) aw = adjTp[(long long)(chunk+1)*NN];
        }

        unsigned wr[2];
        wr[0] = sAdj[buf][wid*16 + g];
        wr[1] = sAdj[buf][wid*16 + g + 8];

#pragma unroll
        for (int s = 0; s < 4; s++) {
            const float4 gva = sGv[chunk*32 + 8*s + t];
            const float4 gvb = sGv[chunk*32 + 8*s + t + 4];
            uint32_t afr[4];
#pragma unroll
            for (int half = 0; half < 2; half++) {
                float s0 = fr[half] + gva.x;
                float p0 = (s0 > 0.f ? ear[half] : ecr[half]) * (s0 > 0.f ? gva.y : gva.z);
                p0 = ((wr[half] >> (8*s + t)) & 1u) ? p0 : 0.f;
                float s1 = fr[half] + gvb.x;
                float p1 = (s1 > 0.f ? ear[half] : ecr[half]) * (s1 > 0.f ? gvb.y : gvb.z);
                p1 = ((wr[half] >> (8*s + t + 4)) & 1u) ? p1 : 0.f;
                afr[half]     = to_tf32_u(p0);
                afr[half + 2] = to_tf32_u(p1);
            }
#pragma unroll
            for (int nt = 0; nt < NT; nt++) {
                uint32_t bf[2];
                float2 bv = *(const float2*)&sBf[buf][s][nt][lane][0];
                bf[0] = __float_as_uint(bv.x); bf[1] = __float_as_uint(bv.y);
                mma_tf32_16x8x8(acc[nt], afr, bf);
            }
            mma_tf32_16x8x8(accS, afr, bone);
        }
    }

    if (t == 0) {
        sS[wid*16 + g]     = accS[0];
        sS[wid*16 + g + 8] = accS[2];
    }
    __syncthreads();

#pragma unroll
    for (int half = 0; half < 2; half++) {
        int lrow = wid*16 + g + 8*half;
        int grow = i0 + lrow;
        float isv = 1.0f / fmaxf(sS[lrow], 1e-30f);
#pragma unroll
        for (int nt = 0; nt < NT; nt++) {
            float v0 = acc[nt][half*2+0] * isv;
            float v1 = acc[nt][half*2+1] * isv;
            if (LAYER == 1) {
                v0 = v0 > 0.f ? v0 : expm1f(v0);
                v1 = v1 > 0.f ? v1 : expm1f(v1);
                float* o = d_hcat + ((long long)(b*NN + grow))*(NHEADS*NHID) + h*NHID + nt*8 + t*2;
                *(float2*)o = make_float2(v0, v1);
            } else {
                float* o = dout + ((long long)(b*NN + grow))*NCLASS + nt*8 + t*2;
                *(float2*)o = make_float2(v0, v1);
            }
        }
    }
}

// ---------------- 4) whx2 via mma.sync: Wh2T, f2/g2(fp32) + exps ----------------
// grid BB*NN/64 = 256, block 128 (4 warps x 16 rows). K=256 in 8 chunks of 32.
__global__ __launch_bounds__(128) void whx2_mma_kernel(const float* __restrict__ Wo,
                                                       const float* __restrict__ ao) {
    __shared__ float sHt[2][32][68];   // [buf][k][row] k-major; bank (4k+r)&31
    __shared__ float sWaf[256], sWag[256];
    __shared__ float sAo[64];
    __shared__ float sT[32][68];       // output transpose staging

    const int tid = threadIdx.x, wid = tid >> 5, lane = tid & 31;
    const int g = lane >> 2, t = lane & 3;
    const long long rowbase = (long long)blockIdx.x * 64;
    const int b = (int)(rowbase >> 10);
    const int j0 = (int)(rowbase & 1023);
    const float* hrow = d_hcat + rowbase * 256;

    if (tid < 64) sAo[tid] = ao[tid];
    __syncthreads();
    // waf = Wo @ a_src, wag = Wo @ a_dst (fp32, redundant per block, tiny)
    for (int k = tid; k < 256; k += 128) {
        const float* wr = Wo + k*NCLASS;
        float f = 0.f, gg = 0.f;
#pragma unroll 8
        for (int c = 0; c < NCLASS; c++) { f += wr[c]*sAo[c]; gg += wr[c]*sAo[NCLASS+c]; }
        sWaf[k] = f; sWag[k] = gg;
    }

    float acc[4][4];
#pragma unroll
    for (int nt = 0; nt < 4; nt++)
#pragma unroll
        for (int c = 0; c < 4; c++) acc[nt][c] = 0.f;
    float pf[2] = {0.f, 0.f}, pg[2] = {0.f, 0.f};   // rows g, g+8 (fp32 f/g path)

    // prologue: A chunk 0 -> regs
    float4 areg[4];
#pragma unroll
    for (int q = 0; q < 4; q++) {
        int idx = tid + 128*q; int r = idx >> 3, c4 = idx & 7;
        areg[q] = *(const float4*)(hrow + (long long)r*256 + c4*4);
    }

#pragma unroll 1
    for (int kc = 0; kc < 8; kc++) {
        const int buf = kc & 1;
        // stage A tile k-major
#pragma unroll
        for (int q = 0; q < 4; q++) {
            int idx = tid + 128*q; int r = idx >> 3, c4 = idx & 7;
            sHt[buf][c4*4+0][r] = areg[q].x;
            sHt[buf][c4*4+1][r] = areg[q].y;
            sHt[buf][c4*4+2][r] = areg[q].z;
            sHt[buf][c4*4+3][r] = areg[q].w;
        }
        __syncthreads();
        // prefetch next A chunk
        if (kc < 7) {
#pragma unroll
            for (int q = 0; q < 4; q++) {
                int idx = tid + 128*q; int r = idx >> 3, c4 = idx & 7;
                areg[q] = *(const float4*)(hrow + (long long)r*256 + (kc+1)*32 + c4*4);
            }
        }
        // B fragments from gmem (L1-resident Wo), tf32-rounded
        uint32_t bfr[4][4][2];
#pragma unroll
        for (int s = 0; s < 4; s++) {
            int k0 = kc*32 + 8*s + t;
#pragma unroll
            for (int nt = 0; nt < 4; nt++) {
                int n = nt*8 + g;
                bfr[s][nt][0] = to_tf32_u(Wo[k0*NCLASS + n]);
                bfr[s][nt][1] = to_tf32_u(Wo[(k0+4)*NCLASS + n]);
            }
        }
#pragma unroll
        for (int s = 0; s < 4; s++) {
            int rg = wid*16 + g;
            uint32_t afr[4];
            float a0 = sHt[buf][8*s + t][rg];
            float a1 = sHt[buf][8*s + t][rg + 8];
            float a2 = sHt[buf][8*s + t + 4][rg];
            float a3 = sHt[buf][8*s + t + 4][rg + 8];
            afr[0] = __float_as_uint(a0); afr[1] = __float_as_uint(a1);
            afr[2] = __float_as_uint(a2); afr[3] = __float_as_uint(a3);
            // fp32 f/g partials on raw fp32 A values
            float wf0 = sWaf[kc*32 + 8*s + t], wf1 = sWaf[kc*32 + 8*s + t + 4];
            float wg0 = sWag[kc*32 + 8*s + t], wg1 = sWag[kc*32 + 8*s + t + 4];
            pf[0] += a0*wf0 + a2*wf1;  pf[1] += a1*wf0 + a3*wf1;
            pg[0] += a0*wg0 + a2*wg1;  pg[1] += a1*wg0 + a3*wg1;
#pragma unroll
            for (int nt = 0; nt < 4; nt++)
                mma_tf32_16x8x8(acc[nt], afr, bfr[s][nt]);
        }
    }

    // f/g: reduce over t within quads
#pragma unroll
    for (int r = 0; r < 2; r++) {
        pf[r] += __shfl_xor_sync(FULL, pf[r], 1); pg[r] += __shfl_xor_sync(FULL, pg[r], 1);
        pf[r] += __shfl_xor_sync(FULL, pf[r], 2); pg[r] += __shfl_xor_sync(FULL, pg[r], 2);
    }
    if (t == 0) {
#pragma unroll
        for (int r = 0; r < 2; r++) {
            int o = (int)rowbase + wid*16 + g + 8*r;
            d_f2[o] = pf[r];
            d_eac2[o] = make_float2(__expf(pf[r]), __expf(LRA*pf[r]));
            d_gv2[o] = make_float4(pg[r], __expf(pg[r]), __expf(LRA*pg[r]), 0.f);
        }
    }

    // Wh2T: transpose staging (bank 8t+g distinct -> conflict-free), coalesced store
    __syncthreads();
#pragma unroll
    for (int nt = 0; nt < 4; nt++)
#pragma unroll
        for (int c = 0; c < 4; c++) {
            int col = nt*8 + t*2 + (c & 1);
            int lr = wid*16 + g + 8*(c >> 1);
            sT[col][lr] = to_tf32(acc[nt][c]);
        }
    __syncthreads();
    for (int idx = tid; idx < 32*16; idx += 128) {
        int c = idx >> 4, j4 = idx & 15;
        float4 v = make_float4(sT[c][j4*4], sT[c][j4*4+1], sT[c][j4*4+2], sT[c][j4*4+3]);
        *(float4*)(d_Wh2T + ((long long)b*NCLASS + c)*NN + j0 + j4*4) = v;
    }
}

// ---------------- launch ----------------
extern "C" void kernel_launch(void* const* d_in, const int* in_sizes, int n_in,
                              void* d_out, int out_size) {
    (void)in_sizes; (void)n_in; (void)out_size;
    const float* x       = (const float*)d_in[0];
    const int*   adj     = (const int*)  d_in[1];
    const float* W_heads = (const float*)d_in[2];
    const float* a_heads = (const float*)d_in[3];
    const float* W_out   = (const float*)d_in[4];
    const float* a_out   = (const float*)d_in[5];
    float* out = (float*)d_out;

    pack_adj_kernel<<<BB*NN/8, 256>>>(adj);
    whx1_kernel<<<dim3(NN/64, BB, NHEADS), 256>>>(x, W_heads, a_heads);
    pv_mma_kernel<1><<<dim3(NN/128, BB, NHEADS), 256>>>(nullptr);
    whx2_mma_kernel<<<BB*NN/64, 128>>>(W_out, a_out);
    pv_mma_kernel<2><<<dim3(NN/64, BB, 1), 128>>>(out);
}

// round 14
// speedup vs baseline: 1.3716x; 1.0163x over previous
#include <cuda_runtime.h>
#include <math.h>
#include <stdint.h>

#define BB 16
#define NN 1024
#define NHEADS 4
#define FIN 64
#define NHID 64
#define NCLASS 32
#define LRA 0.2f
#define FULL 0xffffffffu

// ---------------- scratch (device globals; no allocs) ----------------
__device__ __align__(16) float d_Wh1T[NHEADS*BB*NHID*NN];  // [h,b][c][j] 16.8 MB (tf32)
__device__ float d_f1[NHEADS*BB*NN];
__device__ __align__(8)  float2 d_eac1[NHEADS*BB*NN];      // (e^f, e^{0.2f})
__device__ __align__(16) float4 d_gv1[NHEADS*BB*NN];       // (g, e^g, e^{0.2g}, 0)
__device__ __align__(16) float d_hcat[BB*NN*NHEADS*NHID];  // 16.8 MB
__device__ __align__(16) float d_Wh2T[BB*NCLASS*NN];       // [b][c][j] 2 MB (tf32)
__device__ float d_f2[BB*NN];
__device__ __align__(8)  float2 d_eac2[BB*NN];
__device__ __align__(16) float4 d_gv2[BB*NN];
__device__ unsigned d_adjT[BB*(NN/32)*NN];   // [b][word][i]  2 MB

__device__ __forceinline__ float to_tf32(float x) {
    uint32_t r; asm("cvt.rna.tf32.f32 %0, %1;" : "=r"(r) : "f"(x));
    return __uint_as_float(r);
}
__device__ __forceinline__ uint32_t to_tf32_u(float x) {
    uint32_t r; asm("cvt.rna.tf32.f32 %0, %1;" : "=r"(r) : "f"(x));
    return r;
}
__device__ __forceinline__ void mma_tf32_16x8x8(float* d, const uint32_t* a, const uint32_t* b) {
    asm volatile(
        "mma.sync.aligned.m16n8k8.row.col.f32.tf32.tf32.f32 "
        "{%0,%1,%2,%3}, {%4,%5,%6,%7}, {%8,%9}, {%0,%1,%2,%3};"
        : "+f"(d[0]), "+f"(d[1]), "+f"(d[2]), "+f"(d[3])
        : "r"(a[0]), "r"(a[1]), "r"(a[2]), "r"(a[3]), "r"(b[0]), "r"(b[1]));
}

// ---------------- 1) pack adjacency to transposed bitmask ----------------
__global__ void pack_adj_kernel(const int* __restrict__ adj) {
    int warp = (blockIdx.x * blockDim.x + threadIdx.x) >> 5;
    int lane = threadIdx.x & 31;
    if (warp >= BB*NN) return;
    const int* row = adj + (long long)warp * NN;
    int b = warp >> 10, i = warp & 1023;
    unsigned mym = 0;
#pragma unroll
    for (int wb = 0; wb < 4; wb++) {
        int v[8];
#pragma unroll
        for (int u = 0; u < 8; u++) v[u] = row[(wb*8 + u)*32 + lane];
#pragma unroll
        for (int u = 0; u < 8; u++) {
            unsigned m = __ballot_sync(FULL, v[u] > 0);
            if (lane == wb*8 + u) mym = m;
        }
    }
    d_adjT[(b*32 + lane)*NN + i] = mym;
}

// ---------------- 2) Wh1T = (x @ W_heads[h])^T;  f,g + exps ----------------
// grid (NN/64, BB, NHEADS), block 256
__global__ void whx1_kernel(const float* __restrict__ x,
                            const float* __restrict__ Wh,
                            const float* __restrict__ ah) {
    __shared__ __align__(16) float sW[FIN*NHID];   // 16 KB
    __shared__ float sX[64][FIN+1];                // 16.6 KB; reused as transpose buffer
    __shared__ float sA[2*NHID];
    int h = blockIdx.z, b = blockIdx.y, i0 = blockIdx.x*64;
    int tid = threadIdx.x;

    const float4* Wsrc = (const float4*)(Wh + (long long)h*FIN*NHID);
    float4* Wdst = (float4*)sW;
    for (int idx = tid; idx < FIN*NHID/4; idx += 256) Wdst[idx] = Wsrc[idx];
    if (tid < 2*NHID) sA[tid] = ah[h*2*NHID + tid];
    for (int idx = tid; idx < 64*FIN/4; idx += 256) {
        int r = idx >> 4, c4 = idx & 15;
        float4 v = *(const float4*)(x + (long long)(b*NN + i0 + r)*FIN + c4*4);
        sX[r][c4*4+0]=v.x; sX[r][c4*4+1]=v.y; sX[r][c4*4+2]=v.z; sX[r][c4*4+3]=v.w;
    }
    __syncthreads();

    int r = tid >> 2, ct = tid & 3, c0 = ct*16;
    float acc[16];
#pragma unroll
    for (int c = 0; c < 16; c++) acc[c] = 0.f;
#pragma unroll 4
    for (int k = 0; k < FIN; k++) {
        float xv = sX[r][k];
#pragma unroll
        for (int c4 = 0; c4 < 4; c4++) {
            float4 w = *(const float4*)(&sW[k*NHID + c0 + c4*4]);
            acc[c4*4+0] += xv*w.x; acc[c4*4+1] += xv*w.y;
            acc[c4*4+2] += xv*w.z; acc[c4*4+3] += xv*w.w;
        }
    }

    float pf = 0.f, pg = 0.f;
#pragma unroll
    for (int c = 0; c < 16; c++) { pf += acc[c]*sA[c0+c]; pg += acc[c]*sA[NHID+c0+c]; }
    pf += __shfl_xor_sync(FULL, pf, 1); pg += __shfl_xor_sync(FULL, pg, 1);
    pf += __shfl_xor_sync(FULL, pf, 2); pg += __shfl_xor_sync(FULL, pg, 2);
    if (ct == 0) {
        int o = (h*BB+b)*NN + i0 + r;
        d_f1[o] = pf;
        d_eac1[o] = make_float2(__expf(pf), __expf(LRA*pf));
        d_gv1[o] = make_float4(pg, __expf(pg), __expf(LRA*pg), 0.f);
    }

    __syncthreads();
#pragma unroll
    for (int c = 0; c < 16; c++) sX[c0 + c][r] = to_tf32(acc[c]);
    __syncthreads();
    float* WT = d_Wh1T + (long long)(h*BB + b)*NHID*NN;
    for (int idx = tid; idx < 64*16; idx += 256) {
        int c = idx >> 4, j4 = idx & 15;
        float4 v = make_float4(sX[c][j4*4], sX[c][j4*4+1], sX[c][j4*4+2], sX[c][j4*4+3]);
        *(float4*)(WT + (long long)c*NN + i0 + j4*4) = v;
    }
}

// ---------------- 3) PV via mma.sync tf32 + ones-column row sums ----------------
template<int LAYER>
__global__ __launch_bounds__((LAYER == 1) ? 256 : 128)
void pv_mma_kernel(float* __restrict__ dout) {
    constexpr int F    = (LAYER == 1) ? NHID : NCLASS;
    constexpr int MT   = (LAYER == 1) ? 128 : 64;
    constexpr int NTHR = (MT/16) * 32;
    constexpr int NT   = F / 8;
    constexpr int NQ   = (32*F/4) / NTHR;               // = 2
    __shared__ float4 sGv[NN];
    __shared__ float  sF[MT];
    __shared__ float2 sEac[MT];
    __shared__ float  sBf[2][4][NT][32][2];
    __shared__ unsigned sAdj[2][MT];
    __shared__ float  sS[MT];

    const int tid = threadIdx.x, wid = tid >> 5, lane = tid & 31;
    const int g = lane >> 2, t = lane & 3;
    const int b = blockIdx.y, h = blockIdx.z, i0 = blockIdx.x * MT;
    const int hb = (LAYER == 1) ? (h*BB + b) : b;
    const float*  fA  = (LAYER == 1) ? d_f1  : d_f2;
    const float2* eac = (LAYER == 1) ? d_eac1 : d_eac2;
    const float4* gvA = (LAYER == 1) ? d_gv1 : d_gv2;
    const float*  BT  = (LAYER == 1) ? (d_Wh1T + (long long)hb*F*NN)
                                     : (d_Wh2T + (long long)b*F*NN);

    for (int idx = tid; idx < NN; idx += NTHR) sGv[idx] = gvA[(long long)hb*NN + idx];
    if (tid < MT) {
        sF[tid]   = fA[(long long)hb*NN + i0 + tid];
        sEac[tid] = eac[(long long)hb*NN + i0 + tid];
    }
    __syncthreads();

    float fr[2], ear[2], ecr[2];
#pragma unroll
    for (int r = 0; r < 2; r++) {
        int lr = wid*16 + g + 8*r;
        fr[r] = sF[lr]; ear[r] = sEac[lr].x; ecr[r] = sEac[lr].y;
    }

    float acc[NT][4], accS[4];
#pragma unroll
    for (int nt = 0; nt < NT; nt++)
#pragma unroll
        for (int c = 0; c < 4; c++) acc[nt][c] = 0.f;
#pragma unroll
    for (int c = 0; c < 4; c++) accS[c] = 0.f;
    uint32_t bone[2];
    bone[0] = bone[1] = (lane < 4) ? 0x3f800000u : 0u;

    const unsigned* adjTp = d_adjT + (long long)b*32*NN + i0 + tid;

    float4 breg[NQ];
#pragma unroll
    for (int q = 0; q < NQ; q++) {
        int idx = tid + NTHR*q; int n = idx >> 3, k4 = idx & 7;
        breg[q] = *(const float4*)(BT + (long long)n*NN + k4*4);
    }
    unsigned aw = (tid < MT) ? adjTp[0] : 0u;

#pragma unroll 1
    for (int chunk = 0; chunk < 32; chunk++) {
        const int buf = chunk & 1;
#pragma unroll
        for (int q = 0; q < NQ; q++) {
            int idx = tid + NTHR*q; int n = idx >> 3, k4 = idx & 7;
            int ks = k4 >> 1, bb = k4 & 1, nt = n >> 3, ln = (n & 7) * 4;
            sBf[buf][ks][nt][ln+0][bb] = breg[q].x;
            sBf[buf][ks][nt][ln+1][bb] = breg[q].y;
            sBf[buf][ks][nt][ln+2][bb] = breg[q].z;
            sBf[buf][ks][nt][ln+3][bb] = breg[q].w;
        }
        if (tid < MT) sAdj[buf][tid] = aw;
        __syncthreads();

        if (chunk < 31) {
#pragma unroll
            for (int q = 0; q < NQ; q++) {
                int idx = tid + NTHR*q; int n = idx >> 3, k4 = idx & 7;
                breg[q] = *(const float4*)(BT + (long long)n*NN + (chunk+1)*32 + k4*4);
            }
            if (tid < MT) aw = adjTp[(long long)(chunk+1)*NN];
        }

        unsigned wr[2];
        wr[0] = sAdj[buf][wid*16 + g];
        wr[1] = sAdj[buf][wid*16 + g + 8];

#pragma unroll
        for (int s = 0; s < 4; s++) {
            const float4 gva = sGv[chunk*32 + 8*s + t];
            const float4 gvb = sGv[chunk*32 + 8*s + t + 4];
            uint32_t afr[4];
#pragma unroll
            for (int half = 0; half < 2; half++) {
                float s0 = fr[half] + gva.x;
                float p0 = (s0 > 0.f ? ear[half] : ecr[half]) * (s0 > 0.f ? gva.y : gva.z);
                p0 = ((wr[half] >> (8*s + t)) & 1u) ? p0 : 0.f;
                float s1 = fr[half] + gvb.x;
                float p1 = (s1 > 0.f ? ear[half] : ecr[half]) * (s1 > 0.f ? gvb.y : gvb.z);
                p1 = ((wr[half] >> (8*s + t + 4)) & 1u) ? p1 : 0.f;
                afr[half]     = to_tf32_u(p0);
                afr[half + 2] = to_tf32_u(p1);
            }
#pragma unroll
            for (int nt = 0; nt < NT; nt++) {
                uint32_t bf[2];
                float2 bv = *(const float2*)&sBf[buf][s][nt][lane][0];
                bf[0] = __float_as_uint(bv.x); bf[1] = __float_as_uint(bv.y);
                mma_tf32_16x8x8(acc[nt], afr, bf);
            }
            mma_tf32_16x8x8(accS, afr, bone);
        }
    }

    if (t == 0) {
        sS[wid*16 + g]     = accS[0];
        sS[wid*16 + g + 8] = accS[2];
    }
    __syncthreads();

#pragma unroll
    for (int half = 0; half < 2; half++) {
        int lrow = wid*16 + g + 8*half;
        int grow = i0 + lrow;
        float isv = 1.0f / fmaxf(sS[lrow], 1e-30f);
#pragma unroll
        for (int nt = 0; nt < NT; nt++) {
            float v0 = acc[nt][half*2+0] * isv;
            float v1 = acc[nt][half*2+1] * isv;
            if (LAYER == 1) {
                v0 = v0 > 0.f ? v0 : expm1f(v0);
                v1 = v1 > 0.f ? v1 : expm1f(v1);
                float* o = d_hcat + ((long long)(b*NN + grow))*(NHEADS*NHID) + h*NHID + nt*8 + t*2;
                *(float2*)o = make_float2(v0, v1);
            } else {
                float* o = dout + ((long long)(b*NN + grow))*NCLASS + nt*8 + t*2;
                *(float2*)o = make_float2(v0, v1);
            }
        }
    }
}

// ---------------- 4) whx2 via mma.sync: WoT in smem, single-buffer A, RNA ----------------
// grid 256, block 128 (4 warps x 16 rows). K=256 in 8 chunks of 32.
// smem layout (flat, 11200 floats = 44.8 KB):
//   [0, 2176)      sHt: k*68 + r     (A tile, k-major, 32 k x 64 rows, stride 68)
//   [0, 2176)      sT : col*68 + lr  (ALIASES sHt; used after loop's trailing sync)
//   [2176, 10624)  sWoT: n*264 + k   (tf32 Wo transposed, 32 n x 256 k, stride 264)
//   [10624, 10880) sWaf  [10880, 11136) sWag  [11136, 11200) sAo
__global__ __launch_bounds__(128) void whx2_mma_kernel(const float* __restrict__ Wo,
                                                       const float* __restrict__ ao) {
    __shared__ float sm[11200];
    float* sWoT = sm + 2176;
    float* sWaf = sm + 10624;
    float* sWag = sm + 10880;
    float* sAo  = sm + 11136;

    const int tid = threadIdx.x, wid = tid >> 5, lane = tid & 31;
    const int g = lane >> 2, t = lane & 3;
    const long long rowbase = (long long)blockIdx.x * 64;
    const int b = (int)(rowbase >> 10);
    const int j0 = (int)(rowbase & 1023);
    const float* hrow = d_hcat + rowbase * 256;

    if (tid < 64) sAo[tid] = ao[tid];
    // Wo -> smem transposed, RNA tf32-rounded (one-time)
    for (int idx4 = tid; idx4 < 2048; idx4 += 128) {
        int row = idx4 >> 3, c4 = idx4 & 7;
        float4 v = *(const float4*)(Wo + row*NCLASS + c4*4);
        sWoT[(c4*4+0)*264 + row] = to_tf32(v.x);
        sWoT[(c4*4+1)*264 + row] = to_tf32(v.y);
        sWoT[(c4*4+2)*264 + row] = to_tf32(v.z);
        sWoT[(c4*4+3)*264 + row] = to_tf32(v.w);
    }
    __syncthreads();
    // waf = Wo @ a_src, wag = Wo @ a_dst (fp32 path for f/g)
    for (int k = tid; k < 256; k += 128) {
        const float* wr = Wo + k*NCLASS;
        float f = 0.f, gg = 0.f;
#pragma unroll 8
        for (int c = 0; c < NCLASS; c++) { f += wr[c]*sAo[c]; gg += wr[c]*sAo[NCLASS+c]; }
        sWaf[k] = f; sWag[k] = gg;
    }

    float acc[4][4];
#pragma unroll
    for (int nt = 0; nt < 4; nt++)
#pragma unroll
        for (int c = 0; c < 4; c++) acc[nt][c] = 0.f;
    float pf[2] = {0.f, 0.f}, pg[2] = {0.f, 0.f};

    // prologue: prefetch chunk 0 into registers
    float4 areg[4];
#pragma unroll
    for (int q = 0; q < 4; q++) {
        int idx = tid + 128*q; int r = idx >> 3, c4 = idx & 7;
        areg[q] = *(const float4*)(hrow + (long long)r*256 + c4*4);
    }

#pragma unroll 1
    for (int kc = 0; kc < 8; kc++) {
        // stage A tile k-major (single buffer)
#pragma unroll
        for (int q = 0; q < 4; q++) {
            int idx = tid + 128*q; int r = idx >> 3, c4 = idx & 7;
            sm[(c4*4+0)*68 + r] = areg[q].x;
            sm[(c4*4+1)*68 + r] = areg[q].y;
            sm[(c4*4+2)*68 + r] = areg[q].z;
            sm[(c4*4+3)*68 + r] = areg[q].w;
        }
        __syncthreads();
        // prefetch next chunk into registers (overlaps compute below)
        if (kc < 7) {
#pragma unroll
            for (int q = 0; q < 4; q++) {
                int idx = tid + 128*q; int r = idx >> 3, c4 = idx & 7;
                areg[q] = *(const float4*)(hrow + (long long)r*256 + (kc+1)*32 + c4*4);
            }
        }
        // B fragments from smem
        uint32_t bfr[4][4][2];
#pragma unroll
        for (int s = 0; s < 4; s++) {
            int k0 = kc*32 + 8*s + t;
#pragma unroll
            for (int nt = 0; nt < 4; nt++) {
                int n = nt*8 + g;
                bfr[s][nt][0] = __float_as_uint(sWoT[n*264 + k0]);
                bfr[s][nt][1] = __float_as_uint(sWoT[n*264 + k0 + 4]);
            }
        }
#pragma unroll
        for (int s = 0; s < 4; s++) {
            int rg = wid*16 + g;
            float a0 = sm[(8*s + t)*68 + rg];
            float a1 = sm[(8*s + t)*68 + rg + 8];
            float a2 = sm[(8*s + t + 4)*68 + rg];
            float a3 = sm[(8*s + t + 4)*68 + rg + 8];
            uint32_t afr[4];
            afr[0] = to_tf32_u(a0); afr[1] = to_tf32_u(a1);
            afr[2] = to_tf32_u(a2); afr[3] = to_tf32_u(a3);
            float wf0 = sWaf[kc*32 + 8*s + t], wf1 = sWaf[kc*32 + 8*s + t + 4];
            float wg0 = sWag[kc*32 + 8*s + t], wg1 = sWag[kc*32 + 8*s + t + 4];
            pf[0] += a0*wf0 + a2*wf1;  pf[1] += a1*wf0 + a3*wf1;
            pg[0] += a0*wg0 + a2*wg1;  pg[1] += a1*wg0 + a3*wg1;
#pragma unroll
            for (int nt = 0; nt < 4; nt++)
                mma_tf32_16x8x8(acc[nt], afr, bfr[s][nt]);
        }
        __syncthreads();   // all sHt reads done before next staging
    }

    // f/g: reduce over t within quads
#pragma unroll
    for (int r = 0; r < 2; r++) {
        pf[r] += __shfl_xor_sync(FULL, pf[r], 1); pg[r] += __shfl_xor_sync(FULL, pg[r], 1);
        pf[r] += __shfl_xor_sync(FULL, pf[r], 2); pg[r] += __shfl_xor_sync(FULL, pg[r], 2);
    }
    if (t == 0) {
#pragma unroll
        for (int r = 0; r < 2; r++) {
            int o = (int)rowbase + wid*16 + g + 8*r;
            d_f2[o] = pf[r];
            d_eac2[o] = make_float2(__expf(pf[r]), __expf(LRA*pf[r]));
            d_gv2[o] = make_float4(pg[r], __expf(pg[r]), __expf(LRA*pg[r]), 0.f);
        }
    }

    // Wh2T: transpose staging (aliases sHt; loop's trailing sync already passed)
#pragma unroll
    for (int nt = 0; nt < 4; nt++)
#pragma unroll
        for (int c = 0; c < 4; c++) {
            int col = nt*8 + t*2 + (c & 1);
            int lr = wid*16 + g + 8*(c >> 1);
            sm[col*68 + lr] = to_tf32(acc[nt][c]);
        }
    __syncthreads();
    for (int idx = tid; idx < 32*16; idx += 128) {
        int c = idx >> 4, j4 = idx & 15;
        float4 v = make_float4(sm[c*68 + j4*4], sm[c*68 + j4*4+1],
                               sm[c*68 + j4*4+2], sm[c*68 + j4*4+3]);
        *(float4*)(d_Wh2T + ((long long)b*NCLASS + c)*NN + j0 + j4*4) = v;
    }
}

// ---------------- launch ----------------
extern "C" void kernel_launch(void* const* d_in, const int* in_sizes, int n_in,
                              void* d_out, int out_size) {
    (void)in_sizes; (void)n_in; (void)out_size;
    const float* x       = (const float*)d_in[0];
    const int*   adj     = (const int*)  d_in[1];
    const float* W_heads = (const float*)d_in[2];
    const float* a_heads = (const float*)d_in[3];
    const float* W_out   = (const float*)d_in[4];
    const float* a_out   = (const float*)d_in[5];
    float* out = (float*)d_out;

    pack_adj_kernel<<<BB*NN/8, 256>>>(adj);
    whx1_kernel<<<dim3(NN/64, BB, NHEADS), 256>>>(x, W_heads, a_heads);
    pv_mma_kernel<1><<<dim3(NN/128, BB, NHEADS), 256>>>(nullptr);
    whx2_mma_kernel<<<BB*NN/64, 128>>>(W_out, a_out);
    pv_mma_kernel<2><<<dim3(NN/64, BB, 1), 128>>>(out);
}